// round 13
// baseline (speedup 1.0000x reference)
#include <cuda_runtime.h>

#define S 1024
#define G 10
#define F 5
#define BB 8
#define CC 3
#define KW (2*F+1)
#define TPB 128       // threads per block = columns per tile
#define YT 8          // output rows per block
#define BW 164        // staged buffer row stride (floats), multiple of 4
#define BH 26         // max staged rows

// Scratch for the smoothed, clipped offset field: (B, 2, G, G)
__device__ float g_smooth_dev[BB * 2 * G * G];

// ---------------------------------------------------------------------------
// Kernel 1: 11x11 edge-padded conv of the 10x10 offset fields + clip.
// ---------------------------------------------------------------------------
__global__ void smooth_kernel(const float* __restrict__ ox,
                              const float* __restrict__ oy,
                              const float* __restrict__ w,
                              const int*   __restrict__ mm_raw)
{
    int   mi = mm_raw[0];
    float max_move = (mi > 0 && mi < 1000000) ? (float)mi : __int_as_float(mi);
    float max_offset = 2.0f * max_move / (float)S;

    __shared__ float sw[KW * KW];
    __shared__ float so[G * G];

    int b  = blockIdx.x >> 1;
    int ch = blockIdx.x & 1;
    const float* o = (ch == 0 ? ox : oy) + b * G * G;

    for (int i = threadIdx.x; i < KW * KW; i += blockDim.x) sw[i] = w[i];
    for (int i = threadIdx.x; i < G * G;   i += blockDim.x) so[i] = o[i];
    __syncthreads();

    for (int idx = threadIdx.x; idx < G * G; idx += blockDim.x) {
        int i = idx / G, j = idx % G;
        float acc = 0.0f;
        #pragma unroll
        for (int ky = 0; ky < KW; ky++) {
            int yy = min(max(i + ky - F, 0), G - 1);
            #pragma unroll
            for (int kx = 0; kx < KW; kx++) {
                int xx = min(max(j + kx - F, 0), G - 1);
                acc += so[yy * G + xx] * sw[ky * KW + kx];
            }
        }
        acc *= max_offset;
        acc = fminf(fmaxf(acc, -max_offset), max_offset);
        g_smooth_dev[(b * 2 + ch) * G * G + idx] = acc;
    }
}

// ---------------------------------------------------------------------------
// Kernel 2: 2-D tiled grid sample with shared-memory source staging.
// Phase 1: compute all pixel coords, exact block-wide source bounds.
// If window interior & fits: stage per channel with coalesced LDG.128,
// gather via conflict-free LDS. Else: proven global-gather fallback.
// ---------------------------------------------------------------------------
__global__ __launch_bounds__(TPB, 10)
void deform_kernel(const float* __restrict__ x, float* __restrict__ out)
{
    const int b     = blockIdx.z;
    const int ybase = blockIdx.y * YT;
    const int col   = blockIdx.x * TPB + threadIdx.x;
    const int tid   = threadIdx.x;

    __shared__ float rowg[YT][2 * G];   // y-lerped field rows for this tile
    __shared__ int   red[4];            // xmin, xmax, ymin, ymax (of x0/y0)
    __shared__ float sbuf[BH * BW];     // staged source window (one channel)

    const float scale = (float)G / (float)S;      // exact
    const float hs    = 0.5f * scale - 0.5f;

    if (tid < 4) red[tid] = (tid & 1) ? -(1 << 30) : (1 << 30);

    // Prologue: y-lerp the smoothed field for all YT rows of this tile.
    for (int i = tid; i < YT * 2 * G; i += TPB) {
        int r  = i / (2 * G);
        int t  = i - r * (2 * G);
        int ch = t / G;
        int j  = t - ch * G;
        float sy  = fmaxf(fmaf((float)(ybase + r), scale, hs), 0.0f);
        int   iy0 = min((int)sy, G - 1);
        int   iy1 = min(iy0 + 1, G - 1);
        float wy  = sy - (float)iy0;
        const float* f = g_smooth_dev + (b * 2 + ch) * G * G;
        float a = f[iy0 * G + j];
        float c = f[iy1 * G + j];
        rowg[r][t] = fmaf(c - a, wy, a);
    }
    __syncthreads();

    // Column-invariant field x-lerp coordinates
    const float pxs = 2.0f / (float)(S - 1);
    float sx = fmaxf(fmaf((float)col, scale, hs), 0.0f);
    int   j0 = min((int)sx, G - 1);
    int   j1 = min(j0 + 1, G - 1);
    float wx = sx - (float)j0;
    const float pxv = fmaf((float)col, pxs, -1.0f);   // identity grid x

    const float* img = x   + (size_t)b * CC * S * S;
    float*       op0 = out + (size_t)b * CC * S * S + (size_t)ybase * S + col;

    // ---- Phase 1: coords for all YT pixels + exact bounds ----
    int   pk[YT];
    float axf[YT], ayf[YT];
    int txmin = 1 << 30, txmax = -(1 << 30);
    int tymin = 1 << 30, tymax = -(1 << 30);

    #pragma unroll
    for (int p = 0; p < YT; p++) {
        float ax0 = rowg[p][j0],     ax1 = rowg[p][j1];
        float ay0 = rowg[p][G + j0], ay1 = rowg[p][G + j1];
        float gx = fmaf(ax1 - ax0, wx, ax0);
        float gy = fmaf(ay1 - ay0, wx, ay0);

        float g0 = fminf(fmaxf(gx + pxv, -1.0f), 1.0f);
        float g1 = fminf(fmaxf(gy + fmaf((float)(ybase + p), pxs, -1.0f), -1.0f), 1.0f);

        float ixf = fmaf(g0, 512.0f, 511.5f);   // in [-0.5, 1023.5]
        float iyf = fmaf(g1, 512.0f, 511.5f);

        float fx = floorf(ixf), fy = floorf(iyf);
        int x0 = (int)fx, y0 = (int)fy;          // in [-1, 1023]
        axf[p] = ixf - fx;
        ayf[p] = iyf - fy;
        pk[p]  = ((y0 + 1) << 11) | (x0 + 1);

        txmin = min(txmin, x0); txmax = max(txmax, x0);
        tymin = min(tymin, y0); tymax = max(tymax, y0);
    }

    // warp-reduce then shared atomics
    #pragma unroll
    for (int o = 16; o; o >>= 1) {
        txmin = min(txmin, __shfl_xor_sync(0xffffffffu, txmin, o));
        txmax = max(txmax, __shfl_xor_sync(0xffffffffu, txmax, o));
        tymin = min(tymin, __shfl_xor_sync(0xffffffffu, tymin, o));
        tymax = max(tymax, __shfl_xor_sync(0xffffffffu, tymax, o));
    }
    if ((tid & 31) == 0) {
        atomicMin(&red[0], txmin); atomicMax(&red[1], txmax);
        atomicMin(&red[2], tymin); atomicMax(&red[3], tymax);
    }
    __syncthreads();

    const int xmin = red[0], xmax = red[1], ymin = red[2], ymax = red[3];
    const int xb0   = xmin & ~3;
    const int Wneed = xmax + 2 - xb0;       // cols [xb0 .. xmax+1]
    const int Hneed = ymax + 2 - ymin;      // rows [ymin .. ymax+1]
    const bool ok = (xmin >= 0) && (xmax <= S - 2) &&
                    (ymin >= 0) && (ymax <= S - 2) &&
                    (Wneed <= BW) && (Hneed <= BH);

    if (ok) {
        // convert packed coords to smem indices
        #pragma unroll
        for (int p = 0; p < YT; p++) {
            int y0 = (pk[p] >> 11) - 1;
            int x0 = (pk[p] & 2047) - 1;
            pk[p] = (y0 - ymin) * BW + (x0 - xb0);
        }
        const int W4   = (Wneed + 3) >> 2;
        const int wid  = tid >> 5;
        const int lane = tid & 31;

        #pragma unroll
        for (int c = 0; c < CC; c++) {
            __syncthreads();   // prior gather done before overwrite
            const float* im = img + (size_t)c * S * S;
            for (int dy = wid; dy < Hneed; dy += 4) {
                const float4* sr = (const float4*)(im + (size_t)(ymin + dy) * S + xb0);
                float4*       dr = (float4*)(sbuf + dy * BW);
                for (int dx = lane; dx < W4; dx += 32)
                    dr[dx] = sr[dx];
            }
            __syncthreads();

            #pragma unroll
            for (int p = 0; p < YT; p++) {
                float axx = axf[p], ayy = ayf[p];
                float omx = 1.0f - axx, omy = 1.0f - ayy;
                float w00 = omy * omx, w01 = omy * axx;
                float w10 = ayy * omx, w11 = ayy * axx;
                float v00 = sbuf[pk[p]],      v01 = sbuf[pk[p] + 1];
                float v10 = sbuf[pk[p] + BW], v11 = sbuf[pk[p] + BW + 1];
                float acc = w00 * v00;
                acc = fmaf(w01, v01, acc);
                acc = fmaf(w10, v10, acc);
                acc = fmaf(w11, v11, acc);
                op0[(size_t)c * S * S + p * S] = acc;
            }
        }
    } else {
        // -------- fallback: proven global-gather row loop (R12) --------
        for (int r = 0; r < YT; r++) {
            float ax0 = rowg[r][j0],     ax1 = rowg[r][j1];
            float ay0 = rowg[r][G + j0], ay1 = rowg[r][G + j1];
            float gx = fmaf(ax1 - ax0, wx, ax0);
            float gy = fmaf(ay1 - ay0, wx, ay0);

            float g0 = fminf(fmaxf(gx + pxv, -1.0f), 1.0f);
            float g1 = fminf(fmaxf(gy + fmaf((float)(ybase + r), pxs, -1.0f), -1.0f), 1.0f);

            float ixf = fmaf(g0, 512.0f, 511.5f);
            float iyf = fmaf(g1, 512.0f, 511.5f);

            float fx = floorf(ixf), fy = floorf(iyf);
            int x0 = (int)fx, y0 = (int)fy;
            float axx = ixf - fx, ayy = iyf - fy;
            float omx = 1.0f - axx, omy = 1.0f - ayy;

            float w00, w01, w10, w11;
            int   o00, o01, o10, o11;

            bool interior = (x0 >= 0) & (x0 < S - 1) & (y0 >= 0) & (y0 < S - 1);
            if (__all_sync(0xffffffffu, interior)) {
                w00 = omy * omx;  w01 = omy * axx;
                w10 = ayy * omx;  w11 = ayy * axx;
                o00 = (y0 << 10) + x0;
                o01 = o00 + 1;
                o10 = o00 + S;
                o11 = o10 + 1;
            } else {
                float mx0 = (x0 >= 0)    ? 1.0f : 0.0f;
                float mx1 = (x0 < S - 1) ? 1.0f : 0.0f;
                float wy0 = (y0 >= 0)    ? omy  : 0.0f;
                float wy1 = (y0 < S - 1) ? ayy  : 0.0f;
                w00 = wy0 * omx * mx0;
                w01 = wy0 * axx * mx1;
                w10 = wy1 * omx * mx0;
                w11 = wy1 * axx * mx1;
                int xc0 = max(x0, 0);
                int xc1 = min(x0 + 1, S - 1);
                int yc0 = max(y0, 0) << 10;
                int yc1 = min(y0 + 1, S - 1) << 10;
                o00 = yc0 + xc0; o01 = yc0 + xc1;
                o10 = yc1 + xc0; o11 = yc1 + xc1;
            }

            #pragma unroll
            for (int c = 0; c < CC; c++) {
                const float* im = img + (size_t)c * S * S;
                float v = w00 * __ldg(im + o00) + w01 * __ldg(im + o01)
                        + w10 * __ldg(im + o10) + w11 * __ldg(im + o11);
                op0[(size_t)c * S * S + r * S] = v;
            }
        }
    }
}

extern "C" void kernel_launch(void* const* d_in, const int* in_sizes, int n_in,
                              void* d_out, int out_size)
{
    const float* x  = (const float*)d_in[0];
    const float* ox = (const float*)d_in[1];
    const float* oy = (const float*)d_in[2];
    const float* w  = (const float*)d_in[3];
    const int*   mm = (const int*)  d_in[4];

    smooth_kernel<<<BB * 2, 128>>>(ox, oy, w, mm);

    dim3 blk(TPB, 1, 1);
    dim3 grd(S / TPB, S / YT, BB);   // 8 x 128 x 8 = 8192 blocks
    deform_kernel<<<grd, blk>>>(x, (float*)d_out);
}

// round 14
// speedup vs baseline: 1.6463x; 1.6463x over previous
#include <cuda_runtime.h>

#define S 1024
#define G 10
#define F 5
#define BB 8
#define CC 3
#define KW (2*F+1)
#define TPB 128       // threads per block = columns per tile
#define RY 16         // rows per block (y-locality span)

// Scratch for the smoothed, clipped offset field: (B, 2, G, G)
__device__ float g_smooth_dev[BB * 2 * G * G];

// ---------------------------------------------------------------------------
// Kernel 1: 11x11 edge-padded conv of the 10x10 offset fields + clip.
// ---------------------------------------------------------------------------
__global__ void smooth_kernel(const float* __restrict__ ox,
                              const float* __restrict__ oy,
                              const float* __restrict__ w,
                              const int*   __restrict__ mm_raw)
{
    int   mi = mm_raw[0];
    float max_move = (mi > 0 && mi < 1000000) ? (float)mi : __int_as_float(mi);
    float max_offset = 2.0f * max_move / (float)S;

    __shared__ float sw[KW * KW];
    __shared__ float so[G * G];

    int b  = blockIdx.x >> 1;
    int ch = blockIdx.x & 1;
    const float* o = (ch == 0 ? ox : oy) + b * G * G;

    for (int i = threadIdx.x; i < KW * KW; i += blockDim.x) sw[i] = w[i];
    for (int i = threadIdx.x; i < G * G;   i += blockDim.x) so[i] = o[i];
    __syncthreads();

    for (int idx = threadIdx.x; idx < G * G; idx += blockDim.x) {
        int i = idx / G, j = idx % G;
        float acc = 0.0f;
        #pragma unroll
        for (int ky = 0; ky < KW; ky++) {
            int yy = min(max(i + ky - F, 0), G - 1);
            #pragma unroll
            for (int kx = 0; kx < KW; kx++) {
                int xx = min(max(j + kx - F, 0), G - 1);
                acc += so[yy * G + xx] * sw[ky * KW + kx];
            }
        }
        acc *= max_offset;
        acc = fminf(fmaxf(acc, -max_offset), max_offset);
        g_smooth_dev[(b * 2 + ch) * G * G + idx] = acc;
    }
}

// ---------------------------------------------------------------------------
// Kernel 2: 2-D tiled grid sample. Block = 128 cols x 16 rows; thread = one
// column, 16 consecutive rows. Long y-walk maximizes L1 reuse of source
// lines across row iterations. Field x-lerp coords hoisted (column-
// invariant). <=32 regs forced for 64-warp occupancy.
// ---------------------------------------------------------------------------
__global__ __launch_bounds__(TPB, 16)
void deform_kernel(const float* __restrict__ x, float* __restrict__ out)
{
    const int b     = blockIdx.z;
    const int ybase = blockIdx.y * RY;
    const int col   = blockIdx.x * TPB + threadIdx.x;
    const int tid   = threadIdx.x;

    __shared__ float rowg[RY][2 * G];   // y-lerped field rows for this tile

    const float scale = (float)G / (float)S;      // exact
    const float hs    = 0.5f * scale - 0.5f;

    // Prologue: y-lerp the smoothed field for all RY rows of this tile.
    for (int i = tid; i < RY * 2 * G; i += TPB) {
        int r  = i / (2 * G);
        int t  = i - r * (2 * G);
        int ch = t / G;
        int j  = t - ch * G;
        float sy  = fmaxf(fmaf((float)(ybase + r), scale, hs), 0.0f);
        int   iy0 = min((int)sy, G - 1);
        int   iy1 = min(iy0 + 1, G - 1);
        float wy  = sy - (float)iy0;
        const float* f = g_smooth_dev + (b * 2 + ch) * G * G;
        float a = f[iy0 * G + j];
        float c = f[iy1 * G + j];
        rowg[r][t] = fmaf(c - a, wy, a);
    }
    __syncthreads();

    // Column-invariant field x-lerp coordinates (hoisted out of row loop)
    const float pxs = 2.0f / (float)(S - 1);
    float sx = fmaxf(fmaf((float)col, scale, hs), 0.0f);
    int   j0 = min((int)sx, G - 1);
    int   j1 = min(j0 + 1, G - 1);
    float wx = sx - (float)j0;
    const float pxv = fmaf((float)col, pxs, -1.0f);   // identity grid x

    const float* img = x   + (size_t)b * CC * S * S;
    float*       op  = out + (size_t)b * CC * S * S + (size_t)ybase * S + col;

    for (int r = 0; r < RY; r++) {
        // field lerp for this row
        float ax0 = rowg[r][j0],     ax1 = rowg[r][j1];
        float ay0 = rowg[r][G + j0], ay1 = rowg[r][G + j1];
        float gx = fmaf(ax1 - ax0, wx, ax0);
        float gy = fmaf(ay1 - ay0, wx, ay0);

        // identity grid + clip
        float g0 = fminf(fmaxf(gx + pxv, -1.0f), 1.0f);
        float g1 = fminf(fmaxf(gy + fmaf((float)(ybase + r), pxs, -1.0f), -1.0f), 1.0f);

        // source coords: g*512 + 511.5, in [-0.5, 1023.5]
        float ixf = fmaf(g0, 512.0f, 511.5f);
        float iyf = fmaf(g1, 512.0f, 511.5f);

        float fx = floorf(ixf), fy = floorf(iyf);
        int x0 = (int)fx, y0 = (int)fy;      // in [-1, 1023]
        float axx = ixf - fx, ayy = iyf - fy;
        float omx = 1.0f - axx, omy = 1.0f - ayy;

        float w00, w01, w10, w11;
        int   o00, o01, o10, o11;

        bool interior = (x0 >= 0) & (x0 < S - 1) & (y0 >= 0) & (y0 < S - 1);
        if (__all_sync(0xffffffffu, interior)) {
            w00 = omy * omx;
            w01 = omy * axx;
            w10 = ayy * omx;
            w11 = ayy * axx;
            o00 = (y0 << 10) + x0;
            o01 = o00 + 1;
            o10 = o00 + S;
            o11 = o10 + 1;
        } else {
            float mx0 = (x0 >= 0)    ? 1.0f : 0.0f;
            float mx1 = (x0 < S - 1) ? 1.0f : 0.0f;
            float wy0 = (y0 >= 0)    ? omy  : 0.0f;
            float wy1 = (y0 < S - 1) ? ayy  : 0.0f;
            w00 = wy0 * omx * mx0;
            w01 = wy0 * axx * mx1;
            w10 = wy1 * omx * mx0;
            w11 = wy1 * axx * mx1;
            int xc0 = max(x0, 0);
            int xc1 = min(x0 + 1, S - 1);
            int yc0 = max(y0, 0) << 10;
            int yc1 = min(y0 + 1, S - 1) << 10;
            o00 = yc0 + xc0; o01 = yc0 + xc1;
            o10 = yc1 + xc0; o11 = yc1 + xc1;
        }

        float* oc = op + (size_t)r * S;
        #pragma unroll
        for (int c = 0; c < CC; c++) {
            const float* im = img + (size_t)c * S * S;
            float v = w00 * __ldg(im + o00) + w01 * __ldg(im + o01)
                    + w10 * __ldg(im + o10) + w11 * __ldg(im + o11);
            oc[(size_t)c * S * S] = v;
        }
    }
}

extern "C" void kernel_launch(void* const* d_in, const int* in_sizes, int n_in,
                              void* d_out, int out_size)
{
    const float* x  = (const float*)d_in[0];
    const float* ox = (const float*)d_in[1];
    const float* oy = (const float*)d_in[2];
    const float* w  = (const float*)d_in[3];
    const int*   mm = (const int*)  d_in[4];

    smooth_kernel<<<BB * 2, 128>>>(ox, oy, w, mm);

    dim3 blk(TPB, 1, 1);
    dim3 grd(S / TPB, S / RY, BB);   // 8 x 64 x 8 = 4096 blocks
    deform_kernel<<<grd, blk>>>(x, (float*)d_out);
}